// round 15
// baseline (speedup 1.0000x reference)
#include <cuda_runtime.h>
#include <cuda_bf16.h>
#include <math.h>
#include <stdint.h>

#define N_TOK 4096
#define D_DIM 512
#define E_NUM 8
#define H_DIM 256

// ---------------- scratch (static device globals; no allocation) -------------
__device__ int   g_counts[E_NUM];
__device__ int   g_bucket_tok[E_NUM * N_TOK];   // packed tok*2 + slot
__device__ float g_bucket_scr[E_NUM * N_TOK];

// bf16 hi/lo splits
__device__ __nv_bfloat16 g_xh[N_TOK * D_DIM],  g_xl[N_TOK * D_DIM];
__device__ __nv_bfloat16 g_sgh[D_DIM * H_DIM], g_sgl[D_DIM * H_DIM];
__device__ __nv_bfloat16 g_suh[D_DIM * H_DIM], g_sul[D_DIM * H_DIM];
__device__ __nv_bfloat16 g_sdh[H_DIM * D_DIM], g_sdl[H_DIM * D_DIM];
__device__ __nv_bfloat16 g_Wgh[E_NUM * D_DIM * H_DIM], g_Wgl[E_NUM * D_DIM * H_DIM];
__device__ __nv_bfloat16 g_Wuh[E_NUM * D_DIM * H_DIM], g_Wul[E_NUM * D_DIM * H_DIM];
__device__ __nv_bfloat16 g_Wdh[E_NUM * H_DIM * D_DIM], g_Wdl[E_NUM * H_DIM * D_DIM];
// hidden activations (split for next GEMM)
__device__ __nv_bfloat16 g_h1h[N_TOK * H_DIM], g_h1l[N_TOK * H_DIM];
__device__ __nv_bfloat16 g_hrh[N_TOK * 2 * H_DIM], g_hrl[N_TOK * 2 * H_DIM];
// routed down-proj output rows (fp32)
__device__ float g_yb[N_TOK * 2 * D_DIM];

// ---------------- reset ------------------------------------------------------
__global__ void k_reset() {
    if (threadIdx.x < E_NUM) g_counts[threadIdx.x] = 0;
}

// ---------------- fused fp32 -> bf16 hi/lo split (all tensors, one launch) ----
#define SPL_X   524288
#define SPL_SG  557056
#define SPL_SU  589824
#define SPL_SD  622592
#define SPL_WG  884736
#define SPL_WU  1146880
#define SPL_TOT 1409024

__global__ void __launch_bounds__(256) k_split_all(
    const float* __restrict__ x,  const float* __restrict__ sg,
    const float* __restrict__ su, const float* __restrict__ sd,
    const float* __restrict__ wg, const float* __restrict__ wu,
    const float* __restrict__ wd) {
    int i = blockIdx.x * blockDim.x + threadIdx.x;   // float4 index
    if (i >= SPL_TOT) return;
    const float* src; __nv_bfloat16 *dh, *dl; int base;
    if (i < SPL_X)       { src = x;  dh = g_xh;  dl = g_xl;  base = 0; }
    else if (i < SPL_SG) { src = sg; dh = g_sgh; dl = g_sgl; base = SPL_X; }
    else if (i < SPL_SU) { src = su; dh = g_suh; dl = g_sul; base = SPL_SG; }
    else if (i < SPL_SD) { src = sd; dh = g_sdh; dl = g_sdl; base = SPL_SU; }
    else if (i < SPL_WG) { src = wg; dh = g_Wgh; dl = g_Wgl; base = SPL_SD; }
    else if (i < SPL_WU) { src = wu; dh = g_Wuh; dl = g_Wul; base = SPL_WG; }
    else                 { src = wd; dh = g_Wdh; dl = g_Wdl; base = SPL_WU; }
    int j = i - base;
    float4 v = ((const float4*)src)[j];
    float f[4] = {v.x, v.y, v.z, v.w};
    union { __nv_bfloat162 h2[2]; uint2 u; } Uh, Ul;
#pragma unroll
    for (int p = 0; p < 2; p++) {
        __nv_bfloat16 h0 = __float2bfloat16(f[p * 2 + 0]);
        __nv_bfloat16 h1 = __float2bfloat16(f[p * 2 + 1]);
        __nv_bfloat16 l0 = __float2bfloat16(f[p * 2 + 0] - __bfloat162float(h0));
        __nv_bfloat16 l1 = __float2bfloat16(f[p * 2 + 1] - __bfloat162float(h1));
        Uh.h2[p].x = h0; Uh.h2[p].y = h1;
        Ul.h2[p].x = l0; Ul.h2[p].y = l1;
    }
    *(uint2*)(dh + 4 * (size_t)j) = Uh.u;
    *(uint2*)(dl + 4 * (size_t)j) = Ul.u;
}

// ---------------- router: warp per token ------------------------------------
__global__ void __launch_bounds__(256) k_router(const float* __restrict__ x,
                                                const float* __restrict__ router) {
    int warp = (blockIdx.x * blockDim.x + threadIdx.x) >> 5;
    int lane = threadIdx.x & 31;
    if (warp >= N_TOK) return;
    const float* xr = x + (size_t)warp * D_DIM;
    float acc[E_NUM];
#pragma unroll
    for (int e = 0; e < E_NUM; e++) acc[e] = 0.f;
    for (int d = lane; d < D_DIM; d += 32) {
        float xv = xr[d];
        const float* rr = router + (size_t)d * E_NUM;
#pragma unroll
        for (int e = 0; e < E_NUM; e++) acc[e] += xv * rr[e];
    }
#pragma unroll
    for (int e = 0; e < E_NUM; e++) {
#pragma unroll
        for (int off = 16; off; off >>= 1)
            acc[e] += __shfl_xor_sync(0xffffffffu, acc[e], off);
    }
    if (lane == 0) {
        float mx = acc[0];
#pragma unroll
        for (int e = 1; e < E_NUM; e++) mx = fmaxf(mx, acc[e]);
        float p[E_NUM], s = 0.f;
#pragma unroll
        for (int e = 0; e < E_NUM; e++) { p[e] = expf(acc[e] - mx); s += p[e]; }
        float inv = 1.f / s;
#pragma unroll
        for (int e = 0; e < E_NUM; e++) p[e] *= inv;
        int e0 = 0;
#pragma unroll
        for (int e = 1; e < E_NUM; e++) if (p[e] > p[e0]) e0 = e;
        int e1 = (e0 == 0) ? 1 : 0;
#pragma unroll
        for (int e = 0; e < E_NUM; e++)
            if (e != e0 && e != e1 && p[e] > p[e1]) e1 = e;
        int pos0 = atomicAdd(&g_counts[e0], 1);
        g_bucket_tok[e0 * N_TOK + pos0] = warp * 2 + 0;
        g_bucket_scr[e0 * N_TOK + pos0] = p[e0];
        int pos1 = atomicAdd(&g_counts[e1], 1);
        g_bucket_tok[e1 * N_TOK + pos1] = warp * 2 + 1;
        g_bucket_scr[e1 * N_TOK + pos1] = p[e1];
    }
}

// ---------------- mma / ldmatrix / cp.async helpers ---------------------------
#define MMA_BF16(c, a, b0, b1)                                                  \
    asm volatile(                                                               \
        "mma.sync.aligned.m16n8k16.row.col.f32.bf16.bf16.f32 "                  \
        "{%0,%1,%2,%3},{%4,%5,%6,%7},{%8,%9},{%0,%1,%2,%3};"                    \
        : "+f"((c)[0]), "+f"((c)[1]), "+f"((c)[2]), "+f"((c)[3])                \
        : "r"((a)[0]), "r"((a)[1]), "r"((a)[2]), "r"((a)[3]),                   \
          "r"(b0), "r"(b1))

#define LDMX4(r, p)                                                             \
    asm volatile("ldmatrix.sync.aligned.m8n8.x4.shared.b16 {%0,%1,%2,%3}, [%4];"\
        : "=r"((r)[0]), "=r"((r)[1]), "=r"((r)[2]), "=r"((r)[3]) : "r"(p))

#define LDMX2T(r, p)                                                            \
    asm volatile("ldmatrix.sync.aligned.m8n8.x2.trans.shared.b16 {%0,%1}, [%2];"\
        : "=r"((r)[0]), "=r"((r)[1]) : "r"(p))

#define CP16(dst, src, valid) do {                                              \
    int _sz = (valid) ? 16 : 0;                                                 \
    asm volatile("cp.async.cg.shared.global [%0], [%1], 16, %2;"                \
        :: "r"(dst), "l"(src), "r"(_sz));                                       \
} while (0)
#define CP_COMMIT() asm volatile("cp.async.commit_group;" ::: "memory")
#define CP_WAIT2()  asm volatile("cp.async.wait_group 2;" ::: "memory")
#define CP_WAIT1()  asm volatile("cp.async.wait_group 1;" ::: "memory")
#define CP_WAIT0()  asm volatile("cp.async.wait_group 0;" ::: "memory")

// SMEM strides (bf16 elements)
#define SAK 40    // A tile row stride: 32 + 8 pad  (80B rows)
#define SBN 136   // B tile row stride: 128 + 8 pad (272B rows)
// per-tensor per-stage sizes (elements)
#define A_T 5120          // 128*SAK
#define B_T 4352          // 32*SBN
// gate+up stage layout (elements): Ah | Al | Bgh | Bgl | Buh | Bul
#define GU_A_L   5120
#define GU_B0    10240
#define GU_STAGE 27648
#define GU_SMEM_B (GU_STAGE * 3 * 2)        // 165888 bytes
// down stage layout: Ah | Al | Bh | Bl
#define DN_B0    10240
#define DN_STAGE 18944
#define DN_SMEM_B (DN_STAGE * 3 * 2)        // 113664 bytes

// ---------------- fused gate+up GEMM (bf16x3) + SiLU --------------------------
// z==0: shared; z>=1: routed expert z-1. CTA 128x128, 16 warps (512 thr),
// 3-stage cp.async, prefetch distance 2.
__global__ void __launch_bounds__(512) k_gateup_mma() {
    extern __shared__ __align__(16) __nv_bfloat16 smem[];

    const int z  = blockIdx.z;
    const bool SH = (z == 0);
    const int e  = SH ? 0 : z - 1;
    const int M  = SH ? N_TOK : g_counts[e];
    const int row0 = blockIdx.x * 128;
    if (row0 >= M) return;
    const int col0 = blockIdx.y * 128;

    size_t boff = SH ? 0 : (size_t)e * D_DIM * H_DIM;
    const __nv_bfloat16* Bgh = (SH ? g_sgh : g_Wgh) + boff;
    const __nv_bfloat16* Bgl = (SH ? g_sgl : g_Wgl) + boff;
    const __nv_bfloat16* Buh = (SH ? g_suh : g_Wuh) + boff;
    const __nv_bfloat16* Bul = (SH ? g_sul : g_Wul) + boff;

    const int tid = threadIdx.x, wid = tid >> 5, lane = tid & 31;
    const int lr = lane >> 2, lc = lane & 3;
    const int wm = (wid & 3) * 32, wn = (wid >> 2) * 32;   // 4x4 warp grid (16 warps)

    const uint32_t sb = (uint32_t)__cvta_generic_to_shared(smem);
    const int lm = lane & 15;
    const int lk = (lane >> 4) << 3;

    // A loader (512 thr): row rt = tid>>2 (0..127), 16B piece ro = tid&3
    const int rt = tid >> 2, ro = tid & 3;
    int arow = row0 + rt;
    bool avalid = arow < M;
    int tokA = SH ? (avalid ? arow : 0)
                  : (avalid ? (g_bucket_tok[e * N_TOK + arow] >> 1) : 0);
    // B loader (512 thr): k-row bk = tid>>4 (0..31), 16B piece bo = tid&15
    const int bk = tid >> 4, bo = tid & 15;

    float accg[2][4][4] = {}, accu[2][4][4] = {};

    auto LOADC = [&](int s, int k0) {
        uint32_t st = sb + (uint32_t)(s * GU_STAGE) * 2;
        {
            size_t ga = (size_t)tokA * D_DIM + k0 + ro * 8;
            uint32_t d = st + (uint32_t)(rt * SAK + ro * 8) * 2;
            CP16(d,              g_xh + ga, avalid);
            CP16(d + GU_A_L * 2, g_xl + ga, avalid);
        }
        {
            size_t gb = (size_t)(k0 + bk) * H_DIM + col0 + bo * 8;
            uint32_t db = st + (uint32_t)(GU_B0 + bk * SBN + bo * 8) * 2;
            CP16(db,             Bgh + gb, true);
            CP16(db + B_T * 2,   Bgl + gb, true);
            CP16(db + B_T * 4,   Buh + gb, true);
            CP16(db + B_T * 6,   Bul + gb, true);
        }
    };

    const int NC = D_DIM / 32;   // 16
    LOADC(0, 0);  CP_COMMIT();
    LOADC(1, 32); CP_COMMIT();

    for (int c = 0; c < NC; c++) {
        if (c + 2 < NC) {
            LOADC((c + 2) % 3, (c + 2) * 32);
            CP_COMMIT();
            CP_WAIT2();
        } else if (c + 1 < NC) {
            CP_WAIT1();
        } else {
            CP_WAIT0();
        }
        __syncthreads();

        const uint32_t st = sb + (uint32_t)((c % 3) * GU_STAGE) * 2;
#pragma unroll
        for (int ks = 0; ks < 32; ks += 16) {
            uint32_t aH[2][4], aL[2][4];
#pragma unroll
            for (int mt = 0; mt < 2; mt++) {
                uint32_t aoff = st + (uint32_t)((wm + mt * 16 + lm) * SAK + ks + lk) * 2;
                LDMX4(aH[mt], aoff);
                LDMX4(aL[mt], aoff + GU_A_L * 2);
            }
#pragma unroll
            for (int nt = 0; nt < 4; nt++) {
                uint32_t bofs = st + (uint32_t)(GU_B0 + (ks + lm) * SBN + wn + nt * 8) * 2;
                uint32_t bgh[2], bgl[2], buh[2], bul[2];
                LDMX2T(bgh, bofs);
                LDMX2T(bgl, bofs + B_T * 2);
                LDMX2T(buh, bofs + B_T * 4);
                LDMX2T(bul, bofs + B_T * 6);
#pragma unroll
                for (int mt = 0; mt < 2; mt++) {
                    MMA_BF16(accg[mt][nt], aH[mt], bgh[0], bgh[1]);
                    MMA_BF16(accg[mt][nt], aH[mt], bgl[0], bgl[1]);
                    MMA_BF16(accg[mt][nt], aL[mt], bgh[0], bgh[1]);
                    MMA_BF16(accu[mt][nt], aH[mt], buh[0], buh[1]);
                    MMA_BF16(accu[mt][nt], aH[mt], bul[0], bul[1]);
                    MMA_BF16(accu[mt][nt], aL[mt], buh[0], buh[1]);
                }
            }
        }
        __syncthreads();
    }

    // epilogue: h = silu(g)*u, split to bf16 hi/lo
    __nv_bfloat16* Dh = SH ? g_h1h : g_hrh;
    __nv_bfloat16* Dl = SH ? g_h1l : g_hrl;
#pragma unroll
    for (int mt = 0; mt < 2; mt++) {
#pragma unroll
        for (int hh = 0; hh < 2; hh++) {
            int r = row0 + wm + mt * 16 + lr + hh * 8;
            if (r >= M) continue;
            int orow = SH ? r : g_bucket_tok[e * N_TOK + r];
            size_t cb = (size_t)orow * H_DIM + col0 + wn;
#pragma unroll
            for (int nt = 0; nt < 4; nt++) {
                float gg0 = accg[mt][nt][hh * 2], gg1 = accg[mt][nt][hh * 2 + 1];
                float uu0 = accu[mt][nt][hh * 2], uu1 = accu[mt][nt][hh * 2 + 1];
                float h0 = (gg0 / (1.f + expf(-gg0))) * uu0;
                float h1 = (gg1 / (1.f + expf(-gg1))) * uu1;
                __nv_bfloat16 h0h = __float2bfloat16(h0);
                __nv_bfloat16 h1h = __float2bfloat16(h1);
                __nv_bfloat16 h0l = __float2bfloat16(h0 - __bfloat162float(h0h));
                __nv_bfloat16 h1l = __float2bfloat16(h1 - __bfloat162float(h1h));
                __nv_bfloat162 vh; vh.x = h0h; vh.y = h1h;
                __nv_bfloat162 vl; vl.x = h0l; vl.y = h1l;
                *(__nv_bfloat162*)&Dh[cb + nt * 8 + lc * 2] = vh;
                *(__nv_bfloat162*)&Dl[cb + nt * 8 + lc * 2] = vl;
            }
        }
    }
}

// ---------------- down-proj GEMM (bf16x3) -------------------------------------
__global__ void __launch_bounds__(512) k_down_mma(float* __restrict__ Out) {
    extern __shared__ __align__(16) __nv_bfloat16 smem[];

    const int z  = blockIdx.z;
    const bool SH = (z == 0);
    const int e  = SH ? 0 : z - 1;
    const int M  = SH ? N_TOK : g_counts[e];
    const int row0 = blockIdx.x * 128;
    if (row0 >= M) return;
    const int col0 = blockIdx.y * 128;

    size_t boff = SH ? 0 : (size_t)e * H_DIM * D_DIM;
    const __nv_bfloat16* Bh = (SH ? g_sdh : g_Wdh) + boff;
    const __nv_bfloat16* Bl = (SH ? g_sdl : g_Wdl) + boff;
    const __nv_bfloat16* Ah = SH ? g_h1h : g_hrh;
    const __nv_bfloat16* Al = SH ? g_h1l : g_hrl;

    const int tid = threadIdx.x, wid = tid >> 5, lane = tid & 31;
    const int lr = lane >> 2, lc = lane & 3;
    const int wm = (wid & 3) * 32, wn = (wid >> 2) * 32;

    const uint32_t sb = (uint32_t)__cvta_generic_to_shared(smem);
    const int lm = lane & 15;
    const int lk = (lane >> 4) << 3;

    const int rt = tid >> 2, ro = tid & 3;
    int arow = row0 + rt;
    bool avalid = arow < M;
    int tokA = SH ? (avalid ? arow : 0)
                  : (avalid ? g_bucket_tok[e * N_TOK + arow] : 0);
    const int bk = tid >> 4, bo = tid & 15;

    float acc[2][4][4] = {};

    auto LOADC = [&](int s, int k0) {
        uint32_t st = sb + (uint32_t)(s * DN_STAGE) * 2;
        {
            size_t ga = (size_t)tokA * H_DIM + k0 + ro * 8;
            uint32_t d = st + (uint32_t)(rt * SAK + ro * 8) * 2;
            CP16(d,              Ah + ga, avalid);
            CP16(d + GU_A_L * 2, Al + ga, avalid);
        }
        {
            size_t gb = (size_t)(k0 + bk) * D_DIM + col0 + bo * 8;
            uint32_t db = st + (uint32_t)(DN_B0 + bk * SBN + bo * 8) * 2;
            CP16(db,           Bh + gb, true);
            CP16(db + B_T * 2, Bl + gb, true);
        }
    };

    const int NC = H_DIM / 32;   // 8
    LOADC(0, 0);  CP_COMMIT();
    LOADC(1, 32); CP_COMMIT();

    for (int c = 0; c < NC; c++) {
        if (c + 2 < NC) {
            LOADC((c + 2) % 3, (c + 2) * 32);
            CP_COMMIT();
            CP_WAIT2();
        } else if (c + 1 < NC) {
            CP_WAIT1();
        } else {
            CP_WAIT0();
        }
        __syncthreads();

        const uint32_t st = sb + (uint32_t)((c % 3) * DN_STAGE) * 2;
#pragma unroll
        for (int ks = 0; ks < 32; ks += 16) {
            uint32_t aH[2][4], aL[2][4];
#pragma unroll
            for (int mt = 0; mt < 2; mt++) {
                uint32_t aoff = st + (uint32_t)((wm + mt * 16 + lm) * SAK + ks + lk) * 2;
                LDMX4(aH[mt], aoff);
                LDMX4(aL[mt], aoff + GU_A_L * 2);
            }
#pragma unroll
            for (int nt = 0; nt < 4; nt++) {
                uint32_t bofs = st + (uint32_t)(DN_B0 + (ks + lm) * SBN + wn + nt * 8) * 2;
                uint32_t bh[2], bl[2];
                LDMX2T(bh, bofs);
                LDMX2T(bl, bofs + B_T * 2);
#pragma unroll
                for (int mt = 0; mt < 2; mt++) {
                    MMA_BF16(acc[mt][nt], aH[mt], bh[0], bh[1]);
                    MMA_BF16(acc[mt][nt], aH[mt], bl[0], bl[1]);
                    MMA_BF16(acc[mt][nt], aL[mt], bh[0], bh[1]);
                }
            }
        }
        __syncthreads();
    }

#pragma unroll
    for (int mt = 0; mt < 2; mt++) {
#pragma unroll
        for (int hh = 0; hh < 2; hh++) {
            int r = row0 + wm + mt * 16 + lr + hh * 8;
            if (r >= M) continue;
            float scr = 1.f;
            size_t obase;
            float* optr;
            if (!SH) {
                int tok2 = g_bucket_tok[e * N_TOK + r];
                scr   = g_bucket_scr[e * N_TOK + r];
                obase = (size_t)tok2 * D_DIM;
                optr  = g_yb;
            } else {
                obase = (size_t)r * D_DIM;
                optr  = Out;
            }
#pragma unroll
            for (int nt = 0; nt < 4; nt++) {
                float2 v;
                v.x = scr * acc[mt][nt][hh * 2];
                v.y = scr * acc[mt][nt][hh * 2 + 1];
                *(float2*)&optr[obase + col0 + wn + nt * 8 + lc * 2] = v;
            }
        }
    }
}

// ---------------- final combine ---------------------------------------------
__global__ void __launch_bounds__(256) k_final(float* __restrict__ Out) {
    int i = (blockIdx.x * blockDim.x + threadIdx.x) * 4;
    if (i >= N_TOK * D_DIM) return;
    int n = i / D_DIM, d = i % D_DIM;
    float4 o  = *(float4*)(Out + i);
    float4 y0 = *(const float4*)(g_yb + (size_t)(2 * n) * D_DIM + d);
    float4 y1 = *(const float4*)(g_yb + (size_t)(2 * n + 1) * D_DIM + d);
    o.x += y0.x + y1.x;
    o.y += y0.y + y1.y;
    o.z += y0.z + y1.z;
    o.w += y0.w + y1.w;
    *(float4*)(Out + i) = o;
}

// ---------------- launch -----------------------------------------------------
extern "C" void kernel_launch(void* const* d_in, const int* in_sizes, int n_in,
                              void* d_out, int out_size) {
    const float* x           = (const float*)d_in[0];
    const float* router      = (const float*)d_in[1];
    const float* shared_gate = (const float*)d_in[2];
    const float* shared_up   = (const float*)d_in[3];
    const float* shared_down = (const float*)d_in[4];
    const float* W_gate      = (const float*)d_in[5];
    const float* W_up        = (const float*)d_in[6];
    const float* W_down      = (const float*)d_in[7];
    float* out = (float*)d_out;
    (void)in_sizes; (void)n_in; (void)out_size;

    cudaFuncSetAttribute(k_gateup_mma,
                         cudaFuncAttributeMaxDynamicSharedMemorySize, GU_SMEM_B);
    cudaFuncSetAttribute(k_down_mma,
                         cudaFuncAttributeMaxDynamicSharedMemorySize, DN_SMEM_B);

    k_reset<<<1, 32>>>();
    k_router<<<N_TOK / 8, 256>>>(x, router);

    k_split_all<<<SPL_TOT / 256, 256>>>(x, shared_gate, shared_up, shared_down,
                                        W_gate, W_up, W_down);

    // fused shared+routed gate+up (z=0 shared, z=1..8 experts)
    {
        dim3 g(N_TOK / 128, H_DIM / 128, E_NUM + 1);
        k_gateup_mma<<<g, 512, GU_SMEM_B>>>();
    }
    // fused shared+routed down-proj
    {
        dim3 g(N_TOK / 128, D_DIM / 128, E_NUM + 1);
        k_down_mma<<<g, 512, DN_SMEM_B>>>(out);
    }

    k_final<<<(N_TOK * D_DIM / 4 + 255) / 256, 256>>>(out);
}

// round 17
// speedup vs baseline: 1.6313x; 1.6313x over previous
#include <cuda_runtime.h>
#include <cuda_bf16.h>
#include <math.h>
#include <stdint.h>

#define N_TOK 4096
#define D_DIM 512
#define E_NUM 8
#define H_DIM 256

// ---------------- scratch (static device globals; no allocation) -------------
__device__ int   g_counts[E_NUM];
__device__ int   g_bucket_tok[E_NUM * N_TOK];   // packed tok*2 + slot
__device__ float g_bucket_scr[E_NUM * N_TOK];

// bf16 hi/lo splits
__device__ __nv_bfloat16 g_xh[N_TOK * D_DIM],  g_xl[N_TOK * D_DIM];
__device__ __nv_bfloat16 g_sgh[D_DIM * H_DIM], g_sgl[D_DIM * H_DIM];
__device__ __nv_bfloat16 g_suh[D_DIM * H_DIM], g_sul[D_DIM * H_DIM];
__device__ __nv_bfloat16 g_sdh[H_DIM * D_DIM], g_sdl[H_DIM * D_DIM];
__device__ __nv_bfloat16 g_Wgh[E_NUM * D_DIM * H_DIM], g_Wgl[E_NUM * D_DIM * H_DIM];
__device__ __nv_bfloat16 g_Wuh[E_NUM * D_DIM * H_DIM], g_Wul[E_NUM * D_DIM * H_DIM];
__device__ __nv_bfloat16 g_Wdh[E_NUM * H_DIM * D_DIM], g_Wdl[E_NUM * H_DIM * D_DIM];
// hidden activations (split for next GEMM)
__device__ __nv_bfloat16 g_h1h[N_TOK * H_DIM], g_h1l[N_TOK * H_DIM];
__device__ __nv_bfloat16 g_hrh[N_TOK * 2 * H_DIM], g_hrl[N_TOK * 2 * H_DIM];
// routed down-proj output rows (fp32)
__device__ float g_yb[N_TOK * 2 * D_DIM];

// ---------------- reset ------------------------------------------------------
__global__ void k_reset() {
    if (threadIdx.x < E_NUM) g_counts[threadIdx.x] = 0;
}

// ---------------- fused fp32 -> bf16 hi/lo split (all tensors, one launch) ----
#define SPL_X   524288
#define SPL_SG  557056
#define SPL_SU  589824
#define SPL_SD  622592
#define SPL_WG  884736
#define SPL_WU  1146880
#define SPL_TOT 1409024

__global__ void __launch_bounds__(256) k_split_all(
    const float* __restrict__ x,  const float* __restrict__ sg,
    const float* __restrict__ su, const float* __restrict__ sd,
    const float* __restrict__ wg, const float* __restrict__ wu,
    const float* __restrict__ wd) {
    int i = blockIdx.x * blockDim.x + threadIdx.x;   // float4 index
    if (i >= SPL_TOT) return;
    const float* src; __nv_bfloat16 *dh, *dl; int base;
    if (i < SPL_X)       { src = x;  dh = g_xh;  dl = g_xl;  base = 0; }
    else if (i < SPL_SG) { src = sg; dh = g_sgh; dl = g_sgl; base = SPL_X; }
    else if (i < SPL_SU) { src = su; dh = g_suh; dl = g_sul; base = SPL_SG; }
    else if (i < SPL_SD) { src = sd; dh = g_sdh; dl = g_sdl; base = SPL_SU; }
    else if (i < SPL_WG) { src = wg; dh = g_Wgh; dl = g_Wgl; base = SPL_SD; }
    else if (i < SPL_WU) { src = wu; dh = g_Wuh; dl = g_Wul; base = SPL_WG; }
    else                 { src = wd; dh = g_Wdh; dl = g_Wdl; base = SPL_WU; }
    int j = i - base;
    float4 v = ((const float4*)src)[j];
    float f[4] = {v.x, v.y, v.z, v.w};
    union { __nv_bfloat162 h2[2]; uint2 u; } Uh, Ul;
#pragma unroll
    for (int p = 0; p < 2; p++) {
        __nv_bfloat16 h0 = __float2bfloat16(f[p * 2 + 0]);
        __nv_bfloat16 h1 = __float2bfloat16(f[p * 2 + 1]);
        __nv_bfloat16 l0 = __float2bfloat16(f[p * 2 + 0] - __bfloat162float(h0));
        __nv_bfloat16 l1 = __float2bfloat16(f[p * 2 + 1] - __bfloat162float(h1));
        Uh.h2[p].x = h0; Uh.h2[p].y = h1;
        Ul.h2[p].x = l0; Ul.h2[p].y = l1;
    }
    *(uint2*)(dh + 4 * (size_t)j) = Uh.u;
    *(uint2*)(dl + 4 * (size_t)j) = Ul.u;
}

// ---------------- router: warp per token ------------------------------------
__global__ void __launch_bounds__(256) k_router(const float* __restrict__ x,
                                                const float* __restrict__ router) {
    int warp = (blockIdx.x * blockDim.x + threadIdx.x) >> 5;
    int lane = threadIdx.x & 31;
    if (warp >= N_TOK) return;
    const float* xr = x + (size_t)warp * D_DIM;
    float acc[E_NUM];
#pragma unroll
    for (int e = 0; e < E_NUM; e++) acc[e] = 0.f;
    for (int d = lane; d < D_DIM; d += 32) {
        float xv = xr[d];
        const float* rr = router + (size_t)d * E_NUM;
#pragma unroll
        for (int e = 0; e < E_NUM; e++) acc[e] += xv * rr[e];
    }
#pragma unroll
    for (int e = 0; e < E_NUM; e++) {
#pragma unroll
        for (int off = 16; off; off >>= 1)
            acc[e] += __shfl_xor_sync(0xffffffffu, acc[e], off);
    }
    if (lane == 0) {
        float mx = acc[0];
#pragma unroll
        for (int e = 1; e < E_NUM; e++) mx = fmaxf(mx, acc[e]);
        float p[E_NUM], s = 0.f;
#pragma unroll
        for (int e = 0; e < E_NUM; e++) { p[e] = expf(acc[e] - mx); s += p[e]; }
        float inv = 1.f / s;
#pragma unroll
        for (int e = 0; e < E_NUM; e++) p[e] *= inv;
        int e0 = 0;
#pragma unroll
        for (int e = 1; e < E_NUM; e++) if (p[e] > p[e0]) e0 = e;
        int e1 = (e0 == 0) ? 1 : 0;
#pragma unroll
        for (int e = 0; e < E_NUM; e++)
            if (e != e0 && e != e1 && p[e] > p[e1]) e1 = e;
        int pos0 = atomicAdd(&g_counts[e0], 1);
        g_bucket_tok[e0 * N_TOK + pos0] = warp * 2 + 0;
        g_bucket_scr[e0 * N_TOK + pos0] = p[e0];
        int pos1 = atomicAdd(&g_counts[e1], 1);
        g_bucket_tok[e1 * N_TOK + pos1] = warp * 2 + 1;
        g_bucket_scr[e1 * N_TOK + pos1] = p[e1];
    }
}

// ---------------- mma / ldmatrix / cp.async helpers ---------------------------
#define MMA_BF16(c, a, b0, b1)                                                  \
    asm volatile(                                                               \
        "mma.sync.aligned.m16n8k16.row.col.f32.bf16.bf16.f32 "                  \
        "{%0,%1,%2,%3},{%4,%5,%6,%7},{%8,%9},{%0,%1,%2,%3};"                    \
        : "+f"((c)[0]), "+f"((c)[1]), "+f"((c)[2]), "+f"((c)[3])                \
        : "r"((a)[0]), "r"((a)[1]), "r"((a)[2]), "r"((a)[3]),                   \
          "r"(b0), "r"(b1))

#define LDMX4(r, p)                                                             \
    asm volatile("ldmatrix.sync.aligned.m8n8.x4.shared.b16 {%0,%1,%2,%3}, [%4];"\
        : "=r"((r)[0]), "=r"((r)[1]), "=r"((r)[2]), "=r"((r)[3]) : "r"(p))

#define LDMX2T(r, p)                                                            \
    asm volatile("ldmatrix.sync.aligned.m8n8.x2.trans.shared.b16 {%0,%1}, [%2];"\
        : "=r"((r)[0]), "=r"((r)[1]) : "r"(p))

#define CP16(dst, src, valid) do {                                              \
    int _sz = (valid) ? 16 : 0;                                                 \
    asm volatile("cp.async.cg.shared.global [%0], [%1], 16, %2;"                \
        :: "r"(dst), "l"(src), "r"(_sz));                                       \
} while (0)
#define CP_COMMIT() asm volatile("cp.async.commit_group;" ::: "memory")
#define CP_WAIT1()  asm volatile("cp.async.wait_group 1;" ::: "memory")
#define CP_WAIT0()  asm volatile("cp.async.wait_group 0;" ::: "memory")

// ---- gate+up tiles (identical to proven R8 config) ----
#define SAK 40   // A tile row stride: 32 + 8 pad (80B rows, conflict-free)
#define SBN 72   // B tile row stride: 64 + 8 pad (144B rows, conflict-free)
#define A_ST 5120          // 128*SAK
#define B_ST 2304          // 32*SBN
#define GU_AL_OFF   10240
#define GU_B0       20480
#define GU_SMEM_EL  38912
#define GU_SMEM_B   (GU_SMEM_EL * 2)
// ---- down tiles (K-chunk 64) ----
#define DSAK 72            // A row stride: 64 + 8 pad (144B rows, conflict-free)
#define D_A_EL 9216        // 128*DSAK
#define D_B_EL 4608        // 64*SBN
#define DN2_AL 9216        // Al offset within stage (elements)
#define DN2_B0 18432       // B base within stage
#define DN2_STAGE 27648    // 18432 + 2*4608 elements
#define DN2_SMEM_B (DN2_STAGE * 2 * 2)     // 110592 bytes

// ---------------- fused gate+up GEMM (bf16x3) + SiLU --------------------------
// z==0: shared expert; z>=1: routed expert z-1. CTA 128x64, 2-stage cp.async.
__global__ void __launch_bounds__(256, 2) k_gateup_mma() {
    extern __shared__ __align__(16) __nv_bfloat16 smem[];

    const int z  = blockIdx.z;
    const bool SH = (z == 0);
    const int e  = SH ? 0 : z - 1;
    const int M  = SH ? N_TOK : g_counts[e];
    const int row0 = blockIdx.x * 128;
    if (row0 >= M) return;
    const int col0 = blockIdx.y * 64;

    size_t boff = SH ? 0 : (size_t)e * D_DIM * H_DIM;
    const __nv_bfloat16* Bgh = (SH ? g_sgh : g_Wgh) + boff;
    const __nv_bfloat16* Bgl = (SH ? g_sgl : g_Wgl) + boff;
    const __nv_bfloat16* Buh = (SH ? g_suh : g_Wuh) + boff;
    const __nv_bfloat16* Bul = (SH ? g_sul : g_Wul) + boff;

    const int tid = threadIdx.x, wid = tid >> 5, lane = tid & 31;
    const int lr = lane >> 2, lc = lane & 3;
    const int wm = (wid & 3) * 32, wn = (wid >> 2) * 32;

    const uint32_t sb = (uint32_t)__cvta_generic_to_shared(smem);
    const int lm = lane & 15;
    const int lk = (lane >> 4) << 3;

    const int rt = tid >> 2, ro = tid & 3;
    int tokA[2]; bool valA[2];
#pragma unroll
    for (int p = 0; p < 2; p++) {
        int r = row0 + rt + p * 64;
        valA[p] = r < M;
        tokA[p] = SH ? (valA[p] ? r : 0)
                     : (valA[p] ? (g_bucket_tok[e * N_TOK + r] >> 1) : 0);
    }
    const int bk = tid >> 3, bo = tid & 7;

    float accg[2][4][4] = {}, accu[2][4][4] = {};

    auto LOADC = [&](int s, int k0) {
#pragma unroll
        for (int p = 0; p < 2; p++) {
            size_t ga = (size_t)tokA[p] * D_DIM + k0 + ro * 8;
            uint32_t d = sb + (uint32_t)(s * A_ST + (rt + p * 64) * SAK + ro * 8) * 2;
            CP16(d,                g_xh + ga, valA[p]);
            CP16(d + GU_AL_OFF * 2, g_xl + ga, valA[p]);
        }
        size_t gb = (size_t)(k0 + bk) * H_DIM + col0 + bo * 8;
        uint32_t db = sb + (uint32_t)(GU_B0 + s * B_ST + bk * SBN + bo * 8) * 2;
        CP16(db,                 Bgh + gb, true);
        CP16(db + 2 * B_ST * 2,  Bgl + gb, true);
        CP16(db + 4 * B_ST * 2,  Buh + gb, true);
        CP16(db + 6 * B_ST * 2,  Bul + gb, true);
    };

    const int NC = D_DIM / 32;   // 16
    LOADC(0, 0);
    CP_COMMIT();

    for (int c = 0; c < NC; c++) {
        if (c + 1 < NC) {
            LOADC((c + 1) & 1, (c + 1) * 32);
            CP_COMMIT();
            CP_WAIT1();
        } else {
            CP_WAIT0();
        }
        __syncthreads();

        const int s = c & 1;
        const uint32_t aBase  = sb + (uint32_t)(s * A_ST) * 2;
        const uint32_t bBase  = sb + (uint32_t)(GU_B0 + s * B_ST) * 2;
#pragma unroll
        for (int ks = 0; ks < 32; ks += 16) {
            uint32_t aH[2][4], aL[2][4];
#pragma unroll
            for (int mt = 0; mt < 2; mt++) {
                uint32_t aoff = aBase + (uint32_t)((wm + mt * 16 + lm) * SAK + ks + lk) * 2;
                LDMX4(aH[mt], aoff);
                LDMX4(aL[mt], aoff + GU_AL_OFF * 2);
            }
#pragma unroll
            for (int nt = 0; nt < 4; nt++) {
                uint32_t bofs = bBase + (uint32_t)((ks + lm) * SBN + wn + nt * 8) * 2;
                uint32_t bgh[2], bgl[2], buh[2], bul[2];
                LDMX2T(bgh, bofs);
                LDMX2T(bgl, bofs + 2 * B_ST * 2);
                LDMX2T(buh, bofs + 4 * B_ST * 2);
                LDMX2T(bul, bofs + 6 * B_ST * 2);
#pragma unroll
                for (int mt = 0; mt < 2; mt++) {
                    MMA_BF16(accg[mt][nt], aH[mt], bgh[0], bgh[1]);
                    MMA_BF16(accg[mt][nt], aH[mt], bgl[0], bgl[1]);
                    MMA_BF16(accg[mt][nt], aL[mt], bgh[0], bgh[1]);
                    MMA_BF16(accu[mt][nt], aH[mt], buh[0], buh[1]);
                    MMA_BF16(accu[mt][nt], aH[mt], bul[0], bul[1]);
                    MMA_BF16(accu[mt][nt], aL[mt], buh[0], buh[1]);
                }
            }
        }
        __syncthreads();
    }

    // epilogue: h = silu(g)*u, split to bf16 hi/lo
    __nv_bfloat16* Dh = SH ? g_h1h : g_hrh;
    __nv_bfloat16* Dl = SH ? g_h1l : g_hrl;
#pragma unroll
    for (int mt = 0; mt < 2; mt++) {
#pragma unroll
        for (int hh = 0; hh < 2; hh++) {
            int r = row0 + wm + mt * 16 + lr + hh * 8;
            if (r >= M) continue;
            int orow = SH ? r : g_bucket_tok[e * N_TOK + r];
            size_t cb = (size_t)orow * H_DIM + col0 + wn;
#pragma unroll
            for (int nt = 0; nt < 4; nt++) {
                float gg0 = accg[mt][nt][hh * 2], gg1 = accg[mt][nt][hh * 2 + 1];
                float uu0 = accu[mt][nt][hh * 2], uu1 = accu[mt][nt][hh * 2 + 1];
                float h0 = (gg0 / (1.f + expf(-gg0))) * uu0;
                float h1 = (gg1 / (1.f + expf(-gg1))) * uu1;
                __nv_bfloat16 h0h = __float2bfloat16(h0);
                __nv_bfloat16 h1h = __float2bfloat16(h1);
                __nv_bfloat16 h0l = __float2bfloat16(h0 - __bfloat162float(h0h));
                __nv_bfloat16 h1l = __float2bfloat16(h1 - __bfloat162float(h1h));
                __nv_bfloat162 vh; vh.x = h0h; vh.y = h1h;
                __nv_bfloat162 vl; vl.x = h0l; vl.y = h1l;
                *(__nv_bfloat162*)&Dh[cb + nt * 8 + lc * 2] = vh;
                *(__nv_bfloat162*)&Dl[cb + nt * 8 + lc * 2] = vl;
            }
        }
    }
}

// ---------------- down-proj GEMM (bf16x3), K-chunk 64 -------------------------
__global__ void __launch_bounds__(256, 2) k_down_mma(float* __restrict__ Out) {
    extern __shared__ __align__(16) __nv_bfloat16 smem[];

    const int z  = blockIdx.z;
    const bool SH = (z == 0);
    const int e  = SH ? 0 : z - 1;
    const int M  = SH ? N_TOK : g_counts[e];
    const int row0 = blockIdx.x * 128;
    if (row0 >= M) return;
    const int col0 = blockIdx.y * 64;

    size_t boff = SH ? 0 : (size_t)e * H_DIM * D_DIM;
    const __nv_bfloat16* Bh = (SH ? g_sdh : g_Wdh) + boff;
    const __nv_bfloat16* Bl = (SH ? g_sdl : g_Wdl) + boff;
    const __nv_bfloat16* Ah = SH ? g_h1h : g_hrh;
    const __nv_bfloat16* Al = SH ? g_h1l : g_hrl;

    const int tid = threadIdx.x, wid = tid >> 5, lane = tid & 31;
    const int lr = lane >> 2, lc = lane & 3;
    const int wm = (wid & 3) * 32, wn = (wid >> 2) * 32;

    const uint32_t sb = (uint32_t)__cvta_generic_to_shared(smem);
    const int lm = lane & 15;
    const int lk = (lane >> 4) << 3;

    // A loader: row rt = tid>>1 (0..127), half pb = (tid&1)*32 elems (4x16B each)
    const int rt = tid >> 1, pb = (tid & 1) * 32;
    int arow = row0 + rt;
    bool avalid = arow < M;
    int tokA = SH ? (avalid ? arow : 0)
                  : (avalid ? g_bucket_tok[e * N_TOK + arow] : 0);
    // B loader: k-row bk = tid>>2 (0..63), piece pair qb = (tid&3)*16 elems
    const int bk = tid >> 2, qb = (tid & 3) * 16;

    float acc[2][4][4] = {};

    auto LOADC = [&](int s, int k0) {
        uint32_t st = sb + (uint32_t)(s * DN2_STAGE) * 2;
#pragma unroll
        for (int j = 0; j < 4; j++) {
            size_t ga = (size_t)tokA * H_DIM + k0 + pb + j * 8;
            uint32_t d = st + (uint32_t)(rt * DSAK + pb + j * 8) * 2;
            CP16(d,              Ah + ga, avalid);
            CP16(d + DN2_AL * 2, Al + ga, avalid);
        }
#pragma unroll
        for (int j = 0; j < 2; j++) {
            size_t gb = (size_t)(k0 + bk) * D_DIM + col0 + qb + j * 8;
            uint32_t db = st + (uint32_t)(DN2_B0 + bk * SBN + qb + j * 8) * 2;
            CP16(db,             Bh + gb, true);
            CP16(db + D_B_EL * 2, Bl + gb, true);
        }
    };

    const int NC = H_DIM / 64;   // 4
    LOADC(0, 0);
    CP_COMMIT();

    for (int c = 0; c < NC; c++) {
        if (c + 1 < NC) {
            LOADC((c + 1) & 1, (c + 1) * 64);
            CP_COMMIT();
            CP_WAIT1();
        } else {
            CP_WAIT0();
        }
        __syncthreads();

        const uint32_t st = sb + (uint32_t)((c & 1) * DN2_STAGE) * 2;
#pragma unroll
        for (int ks = 0; ks < 64; ks += 16) {
            uint32_t aH[2][4], aL[2][4];
#pragma unroll
            for (int mt = 0; mt < 2; mt++) {
                uint32_t aoff = st + (uint32_t)((wm + mt * 16 + lm) * DSAK + ks + lk) * 2;
                LDMX4(aH[mt], aoff);
                LDMX4(aL[mt], aoff + DN2_AL * 2);
            }
#pragma unroll
            for (int nt = 0; nt < 4; nt++) {
                uint32_t bofs = st + (uint32_t)(DN2_B0 + (ks + lm) * SBN + wn + nt * 8) * 2;
                uint32_t bh[2], bl[2];
                LDMX2T(bh, bofs);
                LDMX2T(bl, bofs + D_B_EL * 2);
#pragma unroll
                for (int mt = 0; mt < 2; mt++) {
                    MMA_BF16(acc[mt][nt], aH[mt], bh[0], bh[1]);
                    MMA_BF16(acc[mt][nt], aH[mt], bl[0], bl[1]);
                    MMA_BF16(acc[mt][nt], aL[mt], bh[0], bh[1]);
                }
            }
        }
        __syncthreads();
    }

#pragma unroll
    for (int mt = 0; mt < 2; mt++) {
#pragma unroll
        for (int hh = 0; hh < 2; hh++) {
            int r = row0 + wm + mt * 16 + lr + hh * 8;
            if (r >= M) continue;
            float scr = 1.f;
            size_t obase;
            float* optr;
            if (!SH) {
                int tok2 = g_bucket_tok[e * N_TOK + r];
                scr   = g_bucket_scr[e * N_TOK + r];
                obase = (size_t)tok2 * D_DIM;
                optr  = g_yb;
            } else {
                obase = (size_t)r * D_DIM;
                optr  = Out;
            }
#pragma unroll
            for (int nt = 0; nt < 4; nt++) {
                float2 v;
                v.x = scr * acc[mt][nt][hh * 2];
                v.y = scr * acc[mt][nt][hh * 2 + 1];
                *(float2*)&optr[obase + col0 + wn + nt * 8 + lc * 2] = v;
            }
        }
    }
}

// ---------------- final combine ---------------------------------------------
__global__ void __launch_bounds__(256) k_final(float* __restrict__ Out) {
    int i = (blockIdx.x * blockDim.x + threadIdx.x) * 4;
    if (i >= N_TOK * D_DIM) return;
    int n = i / D_DIM, d = i % D_DIM;
    float4 o  = *(float4*)(Out + i);
    float4 y0 = *(const float4*)(g_yb + (size_t)(2 * n) * D_DIM + d);
    float4 y1 = *(const float4*)(g_yb + (size_t)(2 * n + 1) * D_DIM + d);
    o.x += y0.x + y1.x;
    o.y += y0.y + y1.y;
    o.z += y0.z + y1.z;
    o.w += y0.w + y1.w;
    *(float4*)(Out + i) = o;
}

// ---------------- launch -----------------------------------------------------
extern "C" void kernel_launch(void* const* d_in, const int* in_sizes, int n_in,
                              void* d_out, int out_size) {
    const float* x           = (const float*)d_in[0];
    const float* router      = (const float*)d_in[1];
    const float* shared_gate = (const float*)d_in[2];
    const float* shared_up   = (const float*)d_in[3];
    const float* shared_down = (const float*)d_in[4];
    const float* W_gate      = (const float*)d_in[5];
    const float* W_up        = (const float*)d_in[6];
    const float* W_down      = (const float*)d_in[7];
    float* out = (float*)d_out;
    (void)in_sizes; (void)n_in; (void)out_size;

    cudaFuncSetAttribute(k_gateup_mma,
                         cudaFuncAttributeMaxDynamicSharedMemorySize, GU_SMEM_B);
    cudaFuncSetAttribute(k_down_mma,
                         cudaFuncAttributeMaxDynamicSharedMemorySize, DN2_SMEM_B);

    k_reset<<<1, 32>>>();
    k_router<<<N_TOK / 8, 256>>>(x, router);

    k_split_all<<<SPL_TOT / 256, 256>>>(x, shared_gate, shared_up, shared_down,
                                        W_gate, W_up, W_down);

    // fused shared+routed gate+up (z=0 shared, z=1..8 experts)
    {
        dim3 g(N_TOK / 128, H_DIM / 64, E_NUM + 1);
        k_gateup_mma<<<g, 256, GU_SMEM_B>>>();
    }
    // fused shared+routed down-proj
    {
        dim3 g(N_TOK / 128, D_DIM / 64, E_NUM + 1);
        k_down_mma<<<g, 256, DN2_SMEM_B>>>(out);
    }

    k_final<<<(N_TOK * D_DIM / 4 + 255) / 256, 256>>>(out);
}